// round 14
// baseline (speedup 1.0000x reference)
#include <cuda_runtime.h>

#define BB 8
#define SS 32
#define PP 8
#define VV 8000
#define DD 128
#define CONCF 5.0f
#define EPSF 1e-8f

#define NT_ATTN 512
#define NQ (VV/4)        /* 2000 float4 per row */

/* ---- gemm config: R11 tiling + 3-stage B pipeline ---- */
#define GTM 32           /* m per CTA = full b */
#define GKSPLIT 50
#define GVT 160          /* v per CTA */
#define GKC 32           /* v per staged chunk */
#define GNCH (GVT/GKC)   /* 5 */
#define ASTR 36          /* padded As row stride (floats), 16B-aligned */

// ---------------- scratch (device globals, no allocations) ----------------
__device__ float g_cn[BB*DD];
__device__ float g_cos[BB*VV];
__device__ float g_Abar[(size_t)BB*SS*VV];    // [B*S, V] (8 MB)

__device__ __forceinline__ float warpReduceSum(float v){
    #pragma unroll
    for (int o = 16; o > 0; o >>= 1) v += __shfl_down_sync(0xffffffffu, v, o);
    return v;
}
__device__ __forceinline__ unsigned long long splat2(float f){
    unsigned long long r; asm("mov.b64 %0, {%1,%1};" : "=l"(r) : "f"(f)); return r;
}
__device__ __forceinline__ void fma2(unsigned long long& a, unsigned long long x, unsigned long long y){
    asm("fma.rn.f32x2 %0, %1, %2, %0;" : "+l"(a) : "l"(x), "l"(y));
}
__device__ __forceinline__ void cpasync16(unsigned s, const void* g){
    asm volatile("cp.async.ca.shared.global [%0], [%1], 16;" :: "r"(s), "l"(g));
}

// ---------------- kernel 1: context + normalize (parallel over s) ----------------
__global__ void __launch_bounds__(1024)
ctx_kernel(const int* __restrict__ concepts,
           const int* __restrict__ clen,
           const int* __restrict__ segl,
           const float* __restrict__ embedw){
    __shared__ float sm[8*DD];
    __shared__ float redn[32];
    int b = blockIdx.x;
    int g = threadIdx.x >> 7;
    int d = threadIdx.x & 127;
    int seg = segl[b];

    float part = 0.f;
    for (int s = g; s < seg; s += 8){
        int bs = b*SS + s;
        int len = clen[bs];
        if (len > 0){
            const int4* ci = (const int4*)(concepts + bs*PP);
            int4 c0 = ci[0], c1 = ci[1];
            float sum = 0.f;
            if (0 < len) sum += __ldg(&embedw[(size_t)c0.x*DD + d]);
            if (1 < len) sum += __ldg(&embedw[(size_t)c0.y*DD + d]);
            if (2 < len) sum += __ldg(&embedw[(size_t)c0.z*DD + d]);
            if (3 < len) sum += __ldg(&embedw[(size_t)c0.w*DD + d]);
            if (4 < len) sum += __ldg(&embedw[(size_t)c1.x*DD + d]);
            if (5 < len) sum += __ldg(&embedw[(size_t)c1.y*DD + d]);
            if (6 < len) sum += __ldg(&embedw[(size_t)c1.z*DD + d]);
            if (7 < len) sum += __ldg(&embedw[(size_t)c1.w*DD + d]);
            part += sum / (float)len;
        }
    }
    sm[g*DD + d] = part;
    __syncthreads();

    float ctx = 0.f;
    #pragma unroll
    for (int k = 0; k < 8; ++k) ctx += sm[k*DD + d];
    ctx /= (float)seg;

    int warp = threadIdx.x >> 5, lane = threadIdx.x & 31;
    float sq = warpReduceSum(ctx*ctx);
    if (lane == 0) redn[warp] = sq;
    __syncthreads();
    float n2 = redn[0] + redn[1] + redn[2] + redn[3];
    if (g == 0) g_cn[b*DD + d] = ctx / fmaxf(sqrtf(n2), EPSF);
}

// ---------------- kernel 2: abs cosine sim + fused output zeroing ----------------
__global__ void cos_kernel(const float* __restrict__ kb, float* __restrict__ out){
    if (blockIdx.x < (BB*SS*DD)/256)
        out[blockIdx.x*256 + threadIdx.x] = 0.f;

    int warp = threadIdx.x >> 5, lane = threadIdx.x & 31;
    int v = blockIdx.x*8 + warp;
    if (v >= VV) return;
    const float4* row4 = (const float4*)(kb + (size_t)v*DD);
    float4 kv = row4[lane];
    float nr = kv.x*kv.x + kv.y*kv.y + kv.z*kv.z + kv.w*kv.w;
    nr = warpReduceSum(nr);
    nr = __shfl_sync(0xffffffffu, nr, 0);
    float inv = 1.0f / fmaxf(sqrtf(nr), EPSF);
    #pragma unroll
    for (int b = 0; b < BB; ++b){
        const float4* cn4 = (const float4*)(g_cn + b*DD);
        float4 c = cn4[lane];
        float dt = kv.x*c.x + kv.y*c.y + kv.z*c.z + kv.w*c.w;
        dt = warpReduceSum(dt);
        if (lane == 0) g_cos[(size_t)b*VV + v] = fabsf(dt)*inv;
    }
}

// ---------------- kernel 3: register-resident fused attention (PDL consumer) ----------------
__global__ void __launch_bounds__(NT_ATTN, 1)
attn_kernel(const int* __restrict__ concepts,
            const int* __restrict__ clen,
            const int* __restrict__ segl,
            const float* __restrict__ edge,
            const float* __restrict__ aff,
            const float* __restrict__ lam){
    __shared__ float redA[2][32];
    __shared__ float redB[2][16];
    int bs = blockIdx.x;
    int b = bs >> 5, s = bs & 31;
    int tid = threadIdx.x;
    int warp = tid >> 5, lane = tid & 31;

    float4 racc[4];
    #pragma unroll
    for (int k = 0; k < 4; ++k) racc[k] = make_float4(0.f, 0.f, 0.f, 0.f);

    int seg = segl[b];
    int len = (s < seg) ? clen[bs] : 0;

    if (len > 0){
        float invden = 1.0f / (float)len;
        const float4* cos4 = (const float4*)(g_cos + (size_t)b*VV);
        const float4* lam4 = (const float4*)lam;
        const float4* aff4 = (const float4*)aff;
        const int*    cp   = concepts + bs*PP;

        // ---- pre-sync independent loads: lam, aff, p=0 edge row ----
        float4 A[4], Bv[4];        // staged first as raw lam/aff
        #pragma unroll
        for (int k = 0; k < 4; ++k){
            int i = tid + k*NT_ATTN;
            if (i < NQ){ A[k] = lam4[i]; Bv[k] = aff4[i]; }
        }
        float4 E[4], F[4];
        {
            int c = __ldg(&cp[0]);
            const float4* r = (const float4*)(edge + (size_t)c*VV);
            #pragma unroll
            for (int k = 0; k < 4; ++k){
                int i = tid + k*NT_ATTN;
                if (i < NQ) E[k] = __ldcs(&r[i]);
            }
        }

        cudaGridDependencySynchronize();   // wait for cos_kernel results

        // ---- post-sync: fold cos into coefficients ----
        #pragma unroll
        for (int k = 0; k < 4; ++k){
            int i = tid + k*NT_ATTN;
            if (i < NQ){
                float4 cf = cos4[i];
                float4 l  = A[k];
                float4 af = Bv[k];
                A[k].x = CONCF*l.x*cf.x; A[k].y = CONCF*l.y*cf.y;
                A[k].z = CONCF*l.z*cf.z; A[k].w = CONCF*l.w*cf.w;
                Bv[k].x = CONCF*(1.f-l.x)*af.x; Bv[k].y = CONCF*(1.f-l.y)*af.y;
                Bv[k].z = CONCF*(1.f-l.z)*af.z; Bv[k].w = CONCF*(1.f-l.w)*af.w;
            }
        }

        for (int p = 0; p < len; ++p){
            int q = p & 1;
            if (p + 1 < len){
                int c = __ldg(&cp[p+1]);
                const float4* r = (const float4*)(edge + (size_t)c*VV);
                #pragma unroll
                for (int k = 0; k < 4; ++k){
                    int i = tid + k*NT_ATTN;
                    if (i < NQ) F[k] = __ldcs(&r[i]);
                }
            }

            float mx = -1e30f, mn = 1e30f;
            #pragma unroll
            for (int k = 0; k < 4; ++k){
                int i = tid + k*NT_ATTN;
                if (i < NQ){
                    mx = fmaxf(mx, fmaxf(fmaxf(E[k].x, E[k].y), fmaxf(E[k].z, E[k].w)));
                    mn = fminf(mn, fminf(fminf(E[k].x, E[k].y), fminf(E[k].z, E[k].w)));
                }
            }
            #pragma unroll
            for (int o = 16; o > 0; o >>= 1){
                mx = fmaxf(mx, __shfl_down_sync(0xffffffffu, mx, o));
                mn = fminf(mn, __shfl_down_sync(0xffffffffu, mn, o));
            }
            if (lane == 0){ redA[q][warp] = mx; redA[q][16 + warp] = mn; }
            __syncthreads();
            float rmx = -1e30f, rmn = 1e30f;
            #pragma unroll
            for (int i = 0; i < 16; ++i){
                rmx = fmaxf(rmx, redA[q][i]);
                rmn = fminf(rmn, redA[q][16 + i]);
            }
            float rng  = rmx - rmn;
            float invr = 1.0f / (rng + ((rng == 0.0f) ? 1.0f : 0.0f));

            float ss = 0.f;
            #pragma unroll
            for (int k = 0; k < 4; ++k){
                int i = tid + k*NT_ATTN;
                if (i < NQ){
                    float4 ex;
                    ex.x = __expf((E[k].x*invr)*A[k].x + ((E[k].x > 0.f) ? Bv[k].x : 0.f));
                    ex.y = __expf((E[k].y*invr)*A[k].y + ((E[k].y > 0.f) ? Bv[k].y : 0.f));
                    ex.z = __expf((E[k].z*invr)*A[k].z + ((E[k].z > 0.f) ? Bv[k].z : 0.f));
                    ex.w = __expf((E[k].w*invr)*A[k].w + ((E[k].w > 0.f) ? Bv[k].w : 0.f));
                    E[k] = ex;
                    ss += (ex.x + ex.y) + (ex.z + ex.w);
                }
            }
            ss = warpReduceSum(ss);
            if (lane == 0) redB[q][warp] = ss;
            __syncthreads();
            float tot = 0.f;
            #pragma unroll
            for (int i = 0; i < 16; ++i) tot += redB[q][i];
            float scale = invden / tot;

            #pragma unroll
            for (int k = 0; k < 4; ++k){
                int i = tid + k*NT_ATTN;
                if (i < NQ){
                    racc[k].x += E[k].x*scale;
                    racc[k].y += E[k].y*scale;
                    racc[k].z += E[k].z*scale;
                    racc[k].w += E[k].w*scale;
                }
            }
            #pragma unroll
            for (int k = 0; k < 4; ++k) E[k] = F[k];
        }
    }

    float4* ob = (float4*)(g_Abar + (size_t)bs*VV);
    #pragma unroll
    for (int k = 0; k < 4; ++k){
        int i = tid + k*NT_ATTN;
        if (i < NQ) ob[i] = racc[k];
    }
}

// ---------------- kernel 4: GEMM out[256,128] = Abar @ kb (PDL consumer) ----------------
// R11 tiling (4m x 4d), 3-stage cp.async B pipeline committed 2 ahead:
// steady-state wait_group 1 leaves one group in flight across the whole next
// compute phase (hides DRAM-path latency the 2-stage wait_group 0 exposed).
__global__ void __launch_bounds__(256, 3)
gemm_kernel(const float* __restrict__ kb,
            const int* __restrict__ segl,
            float* __restrict__ out){
    __shared__ __align__(16) float As[2][GKC*ASTR];   // 4.6 KB x2
    __shared__ __align__(16) float Bs[3][GKC*DD];     // 16 KB x3
    int mt = blockIdx.x;             // == b
    int ks = blockIdx.y;
    int m0 = mt*GTM;
    int seg = segl[mt];
    int tid = threadIdx.x;
    int mg  = tid >> 5;              // warp id -> m group
    int dg  = tid & 31;              // lane    -> d group
    int v0  = ks*GVT;
    bool active = (mg*4 < seg);      // whole-warp skip for masked s rows

    // A loader: 256 threads, am = m row (0..31), avq = float4 index (0..7 = 32 v)
    int am = tid >> 3, avq = tid & 7;
    bool arow = (am < seg);                            // masked rows -> zeros
    const float* aptr = &g_Abar[(size_t)(m0 + am)*VV + v0 + avq*4];
    const float* bptr = &kb[(size_t)v0*DD];

    unsigned bs_base[3];
    bs_base[0] = (unsigned)__cvta_generic_to_shared(&Bs[0][0]);
    bs_base[1] = (unsigned)__cvta_generic_to_shared(&Bs[1][0]);
    bs_base[2] = (unsigned)__cvta_generic_to_shared(&Bs[2][0]);

    // ---- prologue (pre-GDS): B chunks 0 and 1 via cp.async (kb-only) ----
    #pragma unroll
    for (int st = 0; st < 2; ++st){
        #pragma unroll
        for (int j = 0; j < 4; ++j){
            int idx = tid + j*256, bv = idx >> 5, bd = idx & 31;
            cpasync16(bs_base[st] + (unsigned)((bv*DD + bd*4)*4),
                      bptr + (size_t)(st*GKC + bv)*DD + bd*4);
        }
        asm volatile("cp.async.commit_group;");
    }

    cudaGridDependencySynchronize();   // wait for attn_kernel's g_Abar

    {
        float4 rA = arow ? __ldcs((const float4*)aptr)
                         : make_float4(0.f, 0.f, 0.f, 0.f);
        As[0][(avq*4 + 0)*ASTR + am] = rA.x;
        As[0][(avq*4 + 1)*ASTR + am] = rA.y;
        As[0][(avq*4 + 2)*ASTR + am] = rA.z;
        As[0][(avq*4 + 3)*ASTR + am] = rA.w;
        asm volatile("cp.async.wait_group 1;");   // B0 arrived; B1 may fly
    }
    __syncthreads();

    unsigned long long acc[8];
    #pragma unroll
    for (int i = 0; i < 8; ++i) acc[i] = 0ULL;

    #pragma unroll
    for (int c = 0; c < GNCH; ++c){
        // issue B(c+2) two chunks ahead
        if (c + 2 < GNCH){
            int vc = (c + 2)*GKC;
            unsigned bsb = bs_base[(c + 2) % 3];
            #pragma unroll
            for (int j = 0; j < 4; ++j){
                int idx = tid + j*256, bv = idx >> 5, bd = idx & 31;
                cpasync16(bsb + (unsigned)((bv*DD + bd*4)*4),
                          bptr + (size_t)(vc + bv)*DD + bd*4);
            }
            asm volatile("cp.async.commit_group;");
        }
        float4 rA;
        if (c + 1 < GNCH){
            int vc = (c + 1)*GKC;
            rA = arow ? __ldcs((const float4*)(aptr + vc))
                      : make_float4(0.f, 0.f, 0.f, 0.f);
        }
        if (active){
            const float* AsB = As[c & 1];
            const float* BsB = Bs[c % 3];
            #pragma unroll
            for (int v = 0; v < GKC; ++v){
                double2 av = *(const double2*)(AsB + v*ASTR + mg*4);   // (a0,a1),(a2,a3) broadcast
                float4  bv = *(const float4*) (BsB + v*DD  + dg*4);
                unsigned long long a01 = __double_as_longlong(av.x);
                unsigned long long a23 = __double_as_longlong(av.y);
                unsigned long long b0 = splat2(bv.x);
                unsigned long long b1 = splat2(bv.y);
                unsigned long long b2 = splat2(bv.z);
                unsigned long long b3 = splat2(bv.w);
                fma2(acc[0], a01, b0); fma2(acc[1], a01, b1);
                fma2(acc[2], a01, b2); fma2(acc[3], a01, b3);
                fma2(acc[4], a23, b0); fma2(acc[5], a23, b1);
                fma2(acc[6], a23, b2); fma2(acc[7], a23, b3);
            }
        }
        if (c + 1 < GNCH){
            int bb = (c + 1) & 1;
            As[bb][(avq*4 + 0)*ASTR + am] = rA.x;
            As[bb][(avq*4 + 1)*ASTR + am] = rA.y;
            As[bb][(avq*4 + 2)*ASTR + am] = rA.z;
            As[bb][(avq*4 + 3)*ASTR + am] = rA.w;
            // ensure B(c+1) arrived; allow B(c+2) (if committed) to stay in flight
            if (c + 2 < GNCH){ asm volatile("cp.async.wait_group 1;"); }
            else             { asm volatile("cp.async.wait_group 0;"); }
        }
        __syncthreads();
    }

    if (active){
        int mbase = m0 + mg*4;
        int dbase = dg*4;
        #pragma unroll
        for (int mp = 0; mp < 2; ++mp){
            #pragma unroll
            for (int dj = 0; dj < 4; ++dj){
                float lo, hi;
                asm("mov.b64 {%0,%1}, %2;" : "=f"(lo), "=f"(hi) : "l"(acc[mp*4 + dj]));
                atomicAdd(&out[(size_t)(mbase + 2*mp    )*DD + dbase + dj], lo);
                atomicAdd(&out[(size_t)(mbase + 2*mp + 1)*DD + dbase + dj], hi);
            }
        }
    }
}

// ---------------- launch ----------------
extern "C" void kernel_launch(void* const* d_in, const int* in_sizes, int n_in,
                              void* d_out, int out_size){
    (void)in_sizes; (void)n_in; (void)out_size;
    const int*   concepts = (const int*)  d_in[0];
    const int*   clen     = (const int*)  d_in[1];
    const int*   segl     = (const int*)  d_in[2];
    const float* embedw   = (const float*)d_in[3];
    const float* kb       = (const float*)d_in[4];
    const float* edge     = (const float*)d_in[5];
    const float* aff      = (const float*)d_in[6];
    const float* lam      = (const float*)d_in[7];
    float* out = (float*)d_out;

    ctx_kernel <<<BB, 1024>>>(concepts, clen, segl, embedw);
    cos_kernel <<<VV/8, 256>>>(kb, out);

    cudaLaunchAttribute pdl[1];
    pdl[0].id = cudaLaunchAttributeProgrammaticStreamSerialization;
    pdl[0].val.programmaticStreamSerializationAllowed = 1;

    {
        cudaLaunchConfig_t cfg = {};
        cfg.gridDim = dim3(BB*SS); cfg.blockDim = dim3(NT_ATTN);
        cfg.attrs = pdl; cfg.numAttrs = 1;
        cudaLaunchKernelEx(&cfg, attn_kernel, concepts, clen, segl, edge, aff, lam);
    }
    {
        cudaLaunchConfig_t cfg = {};
        cfg.gridDim = dim3(BB, GKSPLIT); cfg.blockDim = dim3(256);
        cfg.attrs = pdl; cfg.numAttrs = 1;
        cudaLaunchKernelEx(&cfg, gemm_kernel, kb, segl, out);
    }
}

// round 15
// speedup vs baseline: 1.1098x; 1.1098x over previous
#include <cuda_runtime.h>

#define BB 8
#define SS 32
#define PP 8
#define VV 8000
#define DD 128
#define CONCF 5.0f
#define EPSF 1e-8f

#define NT_ATTN 512
#define NQ (VV/4)        /* 2000 float4 per row */

/* ---- gemm config: tf32 mma.sync, R11 pipeline skeleton ---- */
#define GTM 32           /* m per CTA = full b */
#define GKSPLIT 50
#define GVT 160          /* v per CTA */
#define GKC 32           /* v per staged chunk */
#define GNCH (GVT/GKC)   /* 5 */
#define ASTR 36          /* As [m][k] stride: ==4 mod 32 -> conflict-free A frags */
#define BSTR 136         /* Bs [k][n] stride: ==8 mod 32 -> conflict-free B frags; 16B mult */

// ---------------- scratch (device globals, no allocations) ----------------
__device__ float g_cn[BB*DD];
__device__ float g_cos[BB*VV];
__device__ float g_Abar[(size_t)BB*SS*VV];    // [B*S, V], tf32-rounded (8 MB)
__device__ float g_kbt[(size_t)VV*DD];        // tf32-rounded kb copy (4 MB)

__device__ __forceinline__ float warpReduceSum(float v){
    #pragma unroll
    for (int o = 16; o > 0; o >>= 1) v += __shfl_down_sync(0xffffffffu, v, o);
    return v;
}
__device__ __forceinline__ void cpasync16(unsigned s, const void* g){
    asm volatile("cp.async.ca.shared.global [%0], [%1], 16;" :: "r"(s), "l"(g));
}
__device__ __forceinline__ float tf32r(float x){
    unsigned u; asm("cvt.rna.tf32.f32 %0, %1;" : "=r"(u) : "f"(x));
    return __uint_as_float(u);
}
__device__ __forceinline__ void mma168(float* d, unsigned a0, unsigned a1, unsigned a2, unsigned a3,
                                       unsigned b0, unsigned b1){
    asm volatile("mma.sync.aligned.m16n8k8.row.col.f32.tf32.tf32.f32 "
                 "{%0,%1,%2,%3}, {%4,%5,%6,%7}, {%8,%9}, {%0,%1,%2,%3};"
                 : "+f"(d[0]), "+f"(d[1]), "+f"(d[2]), "+f"(d[3])
                 : "r"(a0), "r"(a1), "r"(a2), "r"(a3), "r"(b0), "r"(b1));
}

// ---------------- kernel 1: context + normalize (parallel over s) ----------------
__global__ void __launch_bounds__(1024)
ctx_kernel(const int* __restrict__ concepts,
           const int* __restrict__ clen,
           const int* __restrict__ segl,
           const float* __restrict__ embedw){
    __shared__ float sm[8*DD];
    __shared__ float redn[32];
    int b = blockIdx.x;
    int g = threadIdx.x >> 7;
    int d = threadIdx.x & 127;
    int seg = segl[b];

    float part = 0.f;
    for (int s = g; s < seg; s += 8){
        int bs = b*SS + s;
        int len = clen[bs];
        if (len > 0){
            const int4* ci = (const int4*)(concepts + bs*PP);
            int4 c0 = ci[0], c1 = ci[1];
            float sum = 0.f;
            if (0 < len) sum += __ldg(&embedw[(size_t)c0.x*DD + d]);
            if (1 < len) sum += __ldg(&embedw[(size_t)c0.y*DD + d]);
            if (2 < len) sum += __ldg(&embedw[(size_t)c0.z*DD + d]);
            if (3 < len) sum += __ldg(&embedw[(size_t)c0.w*DD + d]);
            if (4 < len) sum += __ldg(&embedw[(size_t)c1.x*DD + d]);
            if (5 < len) sum += __ldg(&embedw[(size_t)c1.y*DD + d]);
            if (6 < len) sum += __ldg(&embedw[(size_t)c1.z*DD + d]);
            if (7 < len) sum += __ldg(&embedw[(size_t)c1.w*DD + d]);
            part += sum / (float)len;
        }
    }
    sm[g*DD + d] = part;
    __syncthreads();

    float ctx = 0.f;
    #pragma unroll
    for (int k = 0; k < 8; ++k) ctx += sm[k*DD + d];
    ctx /= (float)seg;

    int warp = threadIdx.x >> 5, lane = threadIdx.x & 31;
    float sq = warpReduceSum(ctx*ctx);
    if (lane == 0) redn[warp] = sq;
    __syncthreads();
    float n2 = redn[0] + redn[1] + redn[2] + redn[3];
    if (g == 0) g_cn[b*DD + d] = ctx / fmaxf(sqrtf(n2), EPSF);
}

// ---------------- kernel 2: cosine sim + out-zeroing + tf32 kb copy ----------------
__global__ void cos_kernel(const float* __restrict__ kb, float* __restrict__ out){
    if (blockIdx.x < (BB*SS*DD)/256)
        out[blockIdx.x*256 + threadIdx.x] = 0.f;

    int warp = threadIdx.x >> 5, lane = threadIdx.x & 31;
    int v = blockIdx.x*8 + warp;
    if (v >= VV) return;
    const float4* row4 = (const float4*)(kb + (size_t)v*DD);
    float4 kv = row4[lane];

    // tf32-rounded copy for the tensor-core GEMM
    float4 kt;
    kt.x = tf32r(kv.x); kt.y = tf32r(kv.y); kt.z = tf32r(kv.z); kt.w = tf32r(kv.w);
    ((float4*)(g_kbt + (size_t)v*DD))[lane] = kt;

    float nr = kv.x*kv.x + kv.y*kv.y + kv.z*kv.z + kv.w*kv.w;
    nr = warpReduceSum(nr);
    nr = __shfl_sync(0xffffffffu, nr, 0);
    float inv = 1.0f / fmaxf(sqrtf(nr), EPSF);
    #pragma unroll
    for (int b = 0; b < BB; ++b){
        const float4* cn4 = (const float4*)(g_cn + b*DD);
        float4 c = cn4[lane];
        float dt = kv.x*c.x + kv.y*c.y + kv.z*c.z + kv.w*c.w;
        dt = warpReduceSum(dt);
        if (lane == 0) g_cos[(size_t)b*VV + v] = fabsf(dt)*inv;
    }
}

// ---------------- kernel 3: register-resident fused attention (PDL consumer) ----------------
__global__ void __launch_bounds__(NT_ATTN, 1)
attn_kernel(const int* __restrict__ concepts,
            const int* __restrict__ clen,
            const int* __restrict__ segl,
            const float* __restrict__ edge,
            const float* __restrict__ aff,
            const float* __restrict__ lam){
    __shared__ float redA[2][32];
    __shared__ float redB[2][16];
    int bs = blockIdx.x;
    int b = bs >> 5, s = bs & 31;
    int tid = threadIdx.x;
    int warp = tid >> 5, lane = tid & 31;

    float4 racc[4];
    #pragma unroll
    for (int k = 0; k < 4; ++k) racc[k] = make_float4(0.f, 0.f, 0.f, 0.f);

    int seg = segl[b];
    int len = (s < seg) ? clen[bs] : 0;

    if (len > 0){
        float invden = 1.0f / (float)len;
        const float4* cos4 = (const float4*)(g_cos + (size_t)b*VV);
        const float4* lam4 = (const float4*)lam;
        const float4* aff4 = (const float4*)aff;
        const int*    cp   = concepts + bs*PP;

        // pre-sync independent loads: lam, aff, p=0 edge row
        float4 A[4], Bv[4];
        #pragma unroll
        for (int k = 0; k < 4; ++k){
            int i = tid + k*NT_ATTN;
            if (i < NQ){ A[k] = lam4[i]; Bv[k] = aff4[i]; }
        }
        float4 E[4], F[4];
        {
            int c = __ldg(&cp[0]);
            const float4* r = (const float4*)(edge + (size_t)c*VV);
            #pragma unroll
            for (int k = 0; k < 4; ++k){
                int i = tid + k*NT_ATTN;
                if (i < NQ) E[k] = __ldcs(&r[i]);
            }
        }

        cudaGridDependencySynchronize();   // wait for cos_kernel results

        #pragma unroll
        for (int k = 0; k < 4; ++k){
            int i = tid + k*NT_ATTN;
            if (i < NQ){
                float4 cf = cos4[i];
                float4 l  = A[k];
                float4 af = Bv[k];
                A[k].x = CONCF*l.x*cf.x; A[k].y = CONCF*l.y*cf.y;
                A[k].z = CONCF*l.z*cf.z; A[k].w = CONCF*l.w*cf.w;
                Bv[k].x = CONCF*(1.f-l.x)*af.x; Bv[k].y = CONCF*(1.f-l.y)*af.y;
                Bv[k].z = CONCF*(1.f-l.z)*af.z; Bv[k].w = CONCF*(1.f-l.w)*af.w;
            }
        }

        for (int p = 0; p < len; ++p){
            int q = p & 1;
            if (p + 1 < len){
                int c = __ldg(&cp[p+1]);
                const float4* r = (const float4*)(edge + (size_t)c*VV);
                #pragma unroll
                for (int k = 0; k < 4; ++k){
                    int i = tid + k*NT_ATTN;
                    if (i < NQ) F[k] = __ldcs(&r[i]);
                }
            }

            float mx = -1e30f, mn = 1e30f;
            #pragma unroll
            for (int k = 0; k < 4; ++k){
                int i = tid + k*NT_ATTN;
                if (i < NQ){
                    mx = fmaxf(mx, fmaxf(fmaxf(E[k].x, E[k].y), fmaxf(E[k].z, E[k].w)));
                    mn = fminf(mn, fminf(fminf(E[k].x, E[k].y), fminf(E[k].z, E[k].w)));
                }
            }
            #pragma unroll
            for (int o = 16; o > 0; o >>= 1){
                mx = fmaxf(mx, __shfl_down_sync(0xffffffffu, mx, o));
                mn = fminf(mn, __shfl_down_sync(0xffffffffu, mn, o));
            }
            if (lane == 0){ redA[q][warp] = mx; redA[q][16 + warp] = mn; }
            __syncthreads();
            float rmx = -1e30f, rmn = 1e30f;
            #pragma unroll
            for (int i = 0; i < 16; ++i){
                rmx = fmaxf(rmx, redA[q][i]);
                rmn = fminf(rmn, redA[q][16 + i]);
            }
            float rng  = rmx - rmn;
            float invr = 1.0f / (rng + ((rng == 0.0f) ? 1.0f : 0.0f));

            float ss = 0.f;
            #pragma unroll
            for (int k = 0; k < 4; ++k){
                int i = tid + k*NT_ATTN;
                if (i < NQ){
                    float4 ex;
                    ex.x = __expf((E[k].x*invr)*A[k].x + ((E[k].x > 0.f) ? Bv[k].x : 0.f));
                    ex.y = __expf((E[k].y*invr)*A[k].y + ((E[k].y > 0.f) ? Bv[k].y : 0.f));
                    ex.z = __expf((E[k].z*invr)*A[k].z + ((E[k].z > 0.f) ? Bv[k].z : 0.f));
                    ex.w = __expf((E[k].w*invr)*A[k].w + ((E[k].w > 0.f) ? Bv[k].w : 0.f));
                    E[k] = ex;
                    ss += (ex.x + ex.y) + (ex.z + ex.w);
                }
            }
            ss = warpReduceSum(ss);
            if (lane == 0) redB[q][warp] = ss;
            __syncthreads();
            float tot = 0.f;
            #pragma unroll
            for (int i = 0; i < 16; ++i) tot += redB[q][i];
            float scale = invden / tot;

            #pragma unroll
            for (int k = 0; k < 4; ++k){
                int i = tid + k*NT_ATTN;
                if (i < NQ){
                    racc[k].x += E[k].x*scale;
                    racc[k].y += E[k].y*scale;
                    racc[k].z += E[k].z*scale;
                    racc[k].w += E[k].w*scale;
                }
            }
            #pragma unroll
            for (int k = 0; k < 4; ++k) E[k] = F[k];
        }
    }

    // tf32-rounded Abar store (gemm consumes raw bits, no CVT in its hot loop)
    float4* ob = (float4*)(g_Abar + (size_t)bs*VV);
    #pragma unroll
    for (int k = 0; k < 4; ++k){
        int i = tid + k*NT_ATTN;
        if (i < NQ){
            float4 t;
            t.x = tf32r(racc[k].x); t.y = tf32r(racc[k].y);
            t.z = tf32r(racc[k].z); t.w = tf32r(racc[k].w);
            ob[i] = t;
        }
    }
}

// ---------------- kernel 4: tf32 MMA GEMM out[256,128] = Abar @ kbt (PDL consumer) ----------------
// Warp w: mt=w>>2 (m16 tile), ng=w&3 (n32 group). Per k8-step per warp:
// 4 LDS (A frag, banks 4g+c conflict-free) + 8 LDS (B frags, banks 8c+g conflict-free)
// + 4 mma.sync.m16n8k8 -> tensor pipe does the math.
__global__ void __launch_bounds__(256, 3)
gemm_kernel(const float* __restrict__ kb,
            const int* __restrict__ segl,
            float* __restrict__ out){
    __shared__ __align__(16) float As[2][GTM*ASTR];   // [m][k] 4.6 KB x2
    __shared__ __align__(16) float Bs[2][GKC*BSTR];   // [k][n] 17.4 KB x2
    (void)kb;
    int b  = blockIdx.x;
    int ks = blockIdx.y;
    int m0 = b*GTM;
    int seg = segl[b];
    int tid = threadIdx.x;
    int w = tid >> 5, lane = tid & 31;
    int mt = w >> 2;                 // 0..1
    int ng = w & 3;                  // 0..3
    int g = lane >> 2, c = lane & 3; // groupID / threadID_in_group
    int v0 = ks*GVT;
    bool active = (mt*16 < seg);     // warp-level skip of fully-masked m16 tiles

    // A loader: am = m row (0..31), avq = float4 index (0..7 = 32 k)
    int am = tid >> 3, avq = tid & 7;
    bool arow = (am < seg);
    const float* aptr = &g_Abar[(size_t)(m0 + am)*VV + v0 + avq*4];
    const float* bptr = &g_kbt[(size_t)v0*DD];

    unsigned bs_base0 = (unsigned)__cvta_generic_to_shared(&Bs[0][0]);
    unsigned bs_base1 = (unsigned)__cvta_generic_to_shared(&Bs[1][0]);

    // ---- prologue (pre-GDS): B chunk 0 via cp.async (g_kbt ready: cos << attn << gemm) ----
    #pragma unroll
    for (int j = 0; j < 4; ++j){
        int idx = tid + j*256, bv = idx >> 5, bd = idx & 31;
        cpasync16(bs_base0 + (unsigned)((bv*BSTR + bd*4)*4),
                  bptr + (size_t)bv*DD + bd*4);
    }
    asm volatile("cp.async.commit_group;");

    cudaGridDependencySynchronize();   // wait for attn_kernel's g_Abar

    {
        float4 rA = arow ? __ldcs((const float4*)aptr)
                         : make_float4(0.f, 0.f, 0.f, 0.f);
        As[0][am*ASTR + avq*4 + 0] = rA.x;
        As[0][am*ASTR + avq*4 + 1] = rA.y;
        As[0][am*ASTR + avq*4 + 2] = rA.z;
        As[0][am*ASTR + avq*4 + 3] = rA.w;
        asm volatile("cp.async.wait_group 0;");
    }
    __syncthreads();

    float acc[16];
    #pragma unroll
    for (int i = 0; i < 16; ++i) acc[i] = 0.f;

    for (int ch = 0; ch < GNCH; ++ch){
        float4 rA;
        if (ch + 1 < GNCH){
            int vc = (ch + 1)*GKC;
            unsigned bsb = ((ch + 1) & 1) ? bs_base1 : bs_base0;
            #pragma unroll
            for (int j = 0; j < 4; ++j){
                int idx = tid + j*256, bv = idx >> 5, bd = idx & 31;
                cpasync16(bsb + (unsigned)((bv*BSTR + bd*4)*4),
                          bptr + (size_t)(vc + bv)*DD + bd*4);
            }
            asm volatile("cp.async.commit_group;");
            rA = arow ? __ldcs((const float4*)(aptr + vc))
                      : make_float4(0.f, 0.f, 0.f, 0.f);
        }
        if (active){
            const float* AsB = As[ch & 1] + (mt*16)*ASTR;
            const float* BsB = Bs[ch & 1] + ng*32;
            #pragma unroll
            for (int k8 = 0; k8 < GKC/8; ++k8){
                int kk = k8*8;
                unsigned a0 = __float_as_uint(AsB[(g    )*ASTR + kk + c    ]);
                unsigned a1 = __float_as_uint(AsB[(g + 8)*ASTR + kk + c    ]);
                unsigned a2 = __float_as_uint(AsB[(g    )*ASTR + kk + c + 4]);
                unsigned a3 = __float_as_uint(AsB[(g + 8)*ASTR + kk + c + 4]);
                #pragma unroll
                for (int nt = 0; nt < 4; ++nt){
                    unsigned b0 = __float_as_uint(BsB[(kk + c    )*BSTR + nt*8 + g]);
                    unsigned b1 = __float_as_uint(BsB[(kk + c + 4)*BSTR + nt*8 + g]);
                    mma168(acc + nt*4, a0, a1, a2, a3, b0, b1);
                }
            }
        }
        if (ch + 1 < GNCH){
            int bb = (ch + 1) & 1;
            As[bb][am*ASTR + avq*4 + 0] = rA.x;
            As[bb][am*ASTR + avq*4 + 1] = rA.y;
            As[bb][am*ASTR + avq*4 + 2] = rA.z;
            As[bb][am*ASTR + avq*4 + 3] = rA.w;
            asm volatile("cp.async.wait_group 0;");
        }
        __syncthreads();
    }

    if (active){
        int mbase = m0 + mt*16;
        int nbase = ng*32;
        #pragma unroll
        for (int nt = 0; nt < 4; ++nt){
            int col = nbase + nt*8 + 2*c;
            atomicAdd(&out[(size_t)(mbase + g    )*DD + col    ], acc[nt*4 + 0]);
            atomicAdd(&out[(size_t)(mbase + g    )*DD + col + 1], acc[nt*4 + 1]);
            atomicAdd(&out[(size_t)(mbase + g + 8)*DD + col    ], acc[nt*4 + 2]);
            atomicAdd(&out[(size_t)(mbase + g + 8)*DD + col + 1], acc[nt*4 + 3]);
        }
    }
}

// ---------------- launch ----------------
extern "C" void kernel_launch(void* const* d_in, const int* in_sizes, int n_in,
                              void* d_out, int out_size){
    (void)in_sizes; (void)n_in; (void)out_size;
    const int*   concepts = (const int*)  d_in[0];
    const int*   clen     = (const int*)  d_in[1];
    const int*   segl     = (const int*)  d_in[2];
    const float* embedw   = (const float*)d_in[3];
    const float* kb       = (const float*)d_in[4];
    const float* edge     = (const float*)d_in[5];
    const float* aff      = (const float*)d_in[6];
    const float* lam      = (const float*)d_in[7];
    float* out = (float*)d_out;

    ctx_kernel <<<BB, 1024>>>(concepts, clen, segl, embedw);
    cos_kernel <<<VV/8, 256>>>(kb, out);

    cudaLaunchAttribute pdl[1];
    pdl[0].id = cudaLaunchAttributeProgrammaticStreamSerialization;
    pdl[0].val.programmaticStreamSerializationAllowed = 1;

    {
        cudaLaunchConfig_t cfg = {};
        cfg.gridDim = dim3(BB*SS); cfg.blockDim = dim3(NT_ATTN);
        cfg.attrs = pdl; cfg.numAttrs = 1;
        cudaLaunchKernelEx(&cfg, attn_kernel, concepts, clen, segl, edge, aff, lam);
    }
    {
        cudaLaunchConfig_t cfg = {};
        cfg.gridDim = dim3(BB, GKSPLIT); cfg.blockDim = dim3(256);
        cfg.attrs = pdl; cfg.numAttrs = 1;
        cudaLaunchKernelEx(&cfg, gemm_kernel, kb, segl, out);
    }
}

// round 16
// speedup vs baseline: 1.1737x; 1.0576x over previous
#include <cuda_runtime.h>

#define BB 8
#define SS 32
#define PP 8
#define VV 8000
#define DD 128
#define CONCF 5.0f
#define EPSF 1e-8f

#define NT_ATTN 512
#define NQ (VV/4)        /* 2000 float4 per row */

/* ---- gemm config: tf32 mma.sync (R15 best-measured) ---- */
#define GTM 32
#define GKSPLIT 50
#define GVT 160
#define GKC 32
#define GNCH (GVT/GKC)   /* 5 */
#define ASTR 36          /* As [m][k] stride: ==4 mod 32 -> conflict-free A frags */
#define BSTR 136         /* Bs [k][n] stride: ==8 mod 32 -> conflict-free B frags */

// ---------------- scratch (device globals, no allocations) ----------------
__device__ float g_cn[BB*DD];
__device__ float g_cos[BB*VV];
__device__ float g_Abar[(size_t)BB*SS*VV];    // [B*S, V], tf32-rounded (8 MB)
__device__ float g_kbt[(size_t)VV*DD];        // tf32-rounded kb copy (4 MB)

__device__ __forceinline__ float warpReduceSum(float v){
    #pragma unroll
    for (int o = 16; o > 0; o >>= 1) v += __shfl_down_sync(0xffffffffu, v, o);
    return v;
}
__device__ __forceinline__ void cpasync16(unsigned s, const void* g){
    asm volatile("cp.async.ca.shared.global [%0], [%1], 16;" :: "r"(s), "l"(g));
}
__device__ __forceinline__ float tf32r(float x){
    unsigned u; asm("cvt.rna.tf32.f32 %0, %1;" : "=r"(u) : "f"(x));
    return __uint_as_float(u);
}
__device__ __forceinline__ void mma168(float* d, unsigned a0, unsigned a1, unsigned a2, unsigned a3,
                                       unsigned b0, unsigned b1){
    asm volatile("mma.sync.aligned.m16n8k8.row.col.f32.tf32.tf32.f32 "
                 "{%0,%1,%2,%3}, {%4,%5,%6,%7}, {%8,%9}, {%0,%1,%2,%3};"
                 : "+f"(d[0]), "+f"(d[1]), "+f"(d[2]), "+f"(d[3])
                 : "r"(a0), "r"(a1), "r"(a2), "r"(a3), "r"(b0), "r"(b1));
}

// ---------------- kernel 1: context + normalize (parallel over s) ----------------
__global__ void __launch_bounds__(1024)
ctx_kernel(const int* __restrict__ concepts,
           const int* __restrict__ clen,
           const int* __restrict__ segl,
           const float* __restrict__ embedw){
    __shared__ float sm[8*DD];
    __shared__ float redn[32];
    int b = blockIdx.x;
    int g = threadIdx.x >> 7;
    int d = threadIdx.x & 127;
    int seg = segl[b];

    float part = 0.f;
    for (int s = g; s < seg; s += 8){
        int bs = b*SS + s;
        int len = clen[bs];
        if (len > 0){
            const int4* ci = (const int4*)(concepts + bs*PP);
            int4 c0 = ci[0], c1 = ci[1];
            float sum = 0.f;
            if (0 < len) sum += __ldg(&embedw[(size_t)c0.x*DD + d]);
            if (1 < len) sum += __ldg(&embedw[(size_t)c0.y*DD + d]);
            if (2 < len) sum += __ldg(&embedw[(size_t)c0.z*DD + d]);
            if (3 < len) sum += __ldg(&embedw[(size_t)c0.w*DD + d]);
            if (4 < len) sum += __ldg(&embedw[(size_t)c1.x*DD + d]);
            if (5 < len) sum += __ldg(&embedw[(size_t)c1.y*DD + d]);
            if (6 < len) sum += __ldg(&embedw[(size_t)c1.z*DD + d]);
            if (7 < len) sum += __ldg(&embedw[(size_t)c1.w*DD + d]);
            part += sum / (float)len;
        }
    }
    sm[g*DD + d] = part;
    __syncthreads();

    float ctx = 0.f;
    #pragma unroll
    for (int k = 0; k < 8; ++k) ctx += sm[k*DD + d];
    ctx /= (float)seg;

    int warp = threadIdx.x >> 5, lane = threadIdx.x & 31;
    float sq = warpReduceSum(ctx*ctx);
    if (lane == 0) redn[warp] = sq;
    __syncthreads();
    float n2 = redn[0] + redn[1] + redn[2] + redn[3];
    if (g == 0) g_cn[b*DD + d] = ctx / fmaxf(sqrtf(n2), EPSF);
}

// ---------------- kernel 2: cosine sim + out-zero + tf32 kb copy (PDL consumer of ctx) ----------------
// Pre-GDS: everything independent of g_cn (zeroing, kb load, norm, tf32 copy).
__global__ void cos_kernel(const float* __restrict__ kb, float* __restrict__ out){
    if (blockIdx.x < (BB*SS*DD)/256)
        out[blockIdx.x*256 + threadIdx.x] = 0.f;

    int warp = threadIdx.x >> 5, lane = threadIdx.x & 31;
    int v = blockIdx.x*8 + warp;
    if (v >= VV){ cudaGridDependencySynchronize(); return; }
    const float4* row4 = (const float4*)(kb + (size_t)v*DD);
    float4 kv = row4[lane];

    // tf32-rounded copy for the tensor-core GEMM
    float4 kt;
    kt.x = tf32r(kv.x); kt.y = tf32r(kv.y); kt.z = tf32r(kv.z); kt.w = tf32r(kv.w);
    ((float4*)(g_kbt + (size_t)v*DD))[lane] = kt;

    float nr = kv.x*kv.x + kv.y*kv.y + kv.z*kv.z + kv.w*kv.w;
    nr = warpReduceSum(nr);
    nr = __shfl_sync(0xffffffffu, nr, 0);
    float inv = 1.0f / fmaxf(sqrtf(nr), EPSF);

    cudaGridDependencySynchronize();   // wait for ctx_kernel's g_cn

    #pragma unroll
    for (int b = 0; b < BB; ++b){
        const float4* cn4 = (const float4*)(g_cn + b*DD);
        float4 c = cn4[lane];
        float dt = kv.x*c.x + kv.y*c.y + kv.z*c.z + kv.w*c.w;
        dt = warpReduceSum(dt);
        if (lane == 0) g_cos[(size_t)b*VV + v] = fabsf(dt)*inv;
    }
}

// ---------------- kernel 3: register-resident fused attention (PDL consumer) ----------------
// Block-uniform early exit for masked segments (gemm zero-fills those A rows).
__global__ void __launch_bounds__(NT_ATTN, 1)
attn_kernel(const int* __restrict__ concepts,
            const int* __restrict__ clen,
            const int* __restrict__ segl,
            const float* __restrict__ edge,
            const float* __restrict__ aff,
            const float* __restrict__ lam){
    __shared__ float redA[2][32];
    __shared__ float redB[2][16];
    int bs = blockIdx.x;
    int b = bs >> 5, s = bs & 31;
    int tid = threadIdx.x;
    int warp = tid >> 5, lane = tid & 31;

    int seg = segl[b];
    if (s >= seg){                      // block-uniform: exit without store/barriers
        cudaGridDependencySynchronize();
        return;
    }
    int len = clen[bs];

    float4 racc[4];
    #pragma unroll
    for (int k = 0; k < 4; ++k) racc[k] = make_float4(0.f, 0.f, 0.f, 0.f);

    if (len > 0){
        float invden = 1.0f / (float)len;
        const float4* cos4 = (const float4*)(g_cos + (size_t)b*VV);
        const float4* lam4 = (const float4*)lam;
        const float4* aff4 = (const float4*)aff;
        const int*    cp   = concepts + bs*PP;

        // pre-sync independent loads: lam, aff, p=0 edge row
        float4 A[4], Bv[4];
        #pragma unroll
        for (int k = 0; k < 4; ++k){
            int i = tid + k*NT_ATTN;
            if (i < NQ){ A[k] = lam4[i]; Bv[k] = aff4[i]; }
        }
        float4 E[4], F[4];
        {
            int c = __ldg(&cp[0]);
            const float4* r = (const float4*)(edge + (size_t)c*VV);
            #pragma unroll
            for (int k = 0; k < 4; ++k){
                int i = tid + k*NT_ATTN;
                if (i < NQ) E[k] = __ldcs(&r[i]);
            }
        }

        cudaGridDependencySynchronize();   // wait for cos_kernel results

        #pragma unroll
        for (int k = 0; k < 4; ++k){
            int i = tid + k*NT_ATTN;
            if (i < NQ){
                float4 cf = cos4[i];
                float4 l  = A[k];
                float4 af = Bv[k];
                A[k].x = CONCF*l.x*cf.x; A[k].y = CONCF*l.y*cf.y;
                A[k].z = CONCF*l.z*cf.z; A[k].w = CONCF*l.w*cf.w;
                Bv[k].x = CONCF*(1.f-l.x)*af.x; Bv[k].y = CONCF*(1.f-l.y)*af.y;
                Bv[k].z = CONCF*(1.f-l.z)*af.z; Bv[k].w = CONCF*(1.f-l.w)*af.w;
            }
        }

        for (int p = 0; p < len; ++p){
            int q = p & 1;
            if (p + 1 < len){
                int c = __ldg(&cp[p+1]);
                const float4* r = (const float4*)(edge + (size_t)c*VV);
                #pragma unroll
                for (int k = 0; k < 4; ++k){
                    int i = tid + k*NT_ATTN;
                    if (i < NQ) F[k] = __ldcs(&r[i]);
                }
            }

            float mx = -1e30f, mn = 1e30f;
            #pragma unroll
            for (int k = 0; k < 4; ++k){
                int i = tid + k*NT_ATTN;
                if (i < NQ){
                    mx = fmaxf(mx, fmaxf(fmaxf(E[k].x, E[k].y), fmaxf(E[k].z, E[k].w)));
                    mn = fminf(mn, fminf(fminf(E[k].x, E[k].y), fminf(E[k].z, E[k].w)));
                }
            }
            #pragma unroll
            for (int o = 16; o > 0; o >>= 1){
                mx = fmaxf(mx, __shfl_down_sync(0xffffffffu, mx, o));
                mn = fminf(mn, __shfl_down_sync(0xffffffffu, mn, o));
            }
            if (lane == 0){ redA[q][warp] = mx; redA[q][16 + warp] = mn; }
            __syncthreads();
            float rmx = -1e30f, rmn = 1e30f;
            #pragma unroll
            for (int i = 0; i < 16; ++i){
                rmx = fmaxf(rmx, redA[q][i]);
                rmn = fminf(rmn, redA[q][16 + i]);
            }
            float rng  = rmx - rmn;
            float invr = 1.0f / (rng + ((rng == 0.0f) ? 1.0f : 0.0f));

            float ss = 0.f;
            #pragma unroll
            for (int k = 0; k < 4; ++k){
                int i = tid + k*NT_ATTN;
                if (i < NQ){
                    float4 ex;
                    ex.x = __expf((E[k].x*invr)*A[k].x + ((E[k].x > 0.f) ? Bv[k].x : 0.f));
                    ex.y = __expf((E[k].y*invr)*A[k].y + ((E[k].y > 0.f) ? Bv[k].y : 0.f));
                    ex.z = __expf((E[k].z*invr)*A[k].z + ((E[k].z > 0.f) ? Bv[k].z : 0.f));
                    ex.w = __expf((E[k].w*invr)*A[k].w + ((E[k].w > 0.f) ? Bv[k].w : 0.f));
                    E[k] = ex;
                    ss += (ex.x + ex.y) + (ex.z + ex.w);
                }
            }
            ss = warpReduceSum(ss);
            if (lane == 0) redB[q][warp] = ss;
            __syncthreads();
            float tot = 0.f;
            #pragma unroll
            for (int i = 0; i < 16; ++i) tot += redB[q][i];
            float scale = invden / tot;

            #pragma unroll
            for (int k = 0; k < 4; ++k){
                int i = tid + k*NT_ATTN;
                if (i < NQ){
                    racc[k].x += E[k].x*scale;
                    racc[k].y += E[k].y*scale;
                    racc[k].z += E[k].z*scale;
                    racc[k].w += E[k].w*scale;
                }
            }
            #pragma unroll
            for (int k = 0; k < 4; ++k) E[k] = F[k];
        }
    } else {
        cudaGridDependencySynchronize();   // len==0, s<seg: still must store zeros
    }

    // tf32-rounded Abar store (only s < seg rows; gemm zero-fills the rest)
    float4* ob = (float4*)(g_Abar + (size_t)bs*VV);
    #pragma unroll
    for (int k = 0; k < 4; ++k){
        int i = tid + k*NT_ATTN;
        if (i < NQ){
            float4 t;
            t.x = tf32r(racc[k].x); t.y = tf32r(racc[k].y);
            t.z = tf32r(racc[k].z); t.w = tf32r(racc[k].w);
            ob[i] = t;
        }
    }
}

// ---------------- kernel 4: tf32 MMA GEMM out[256,128] = Abar @ kbt (PDL consumer) ----------------
__global__ void __launch_bounds__(256, 3)
gemm_kernel(const float* __restrict__ kb,
            const int* __restrict__ segl,
            float* __restrict__ out){
    __shared__ __align__(16) float As[2][GTM*ASTR];   // [m][k] 4.6 KB x2
    __shared__ __align__(16) float Bs[2][GKC*BSTR];   // [k][n] 17.4 KB x2
    (void)kb;
    int b  = blockIdx.x;
    int ks = blockIdx.y;
    int m0 = b*GTM;
    int seg = segl[b];
    int tid = threadIdx.x;
    int w = tid >> 5, lane = tid & 31;
    int mt = w >> 2;
    int ng = w & 3;
    int g = lane >> 2, c = lane & 3;
    int v0 = ks*GVT;
    bool active = (mt*16 < seg);

    int am = tid >> 3, avq = tid & 7;
    bool arow = (am < seg);
    const float* aptr = &g_Abar[(size_t)(m0 + am)*VV + v0 + avq*4];
    const float* bptr = &g_kbt[(size_t)v0*DD];

    unsigned bs_base0 = (unsigned)__cvta_generic_to_shared(&Bs[0][0]);
    unsigned bs_base1 = (unsigned)__cvta_generic_to_shared(&Bs[1][0]);

    #pragma unroll
    for (int j = 0; j < 4; ++j){
        int idx = tid + j*256, bv = idx >> 5, bd = idx & 31;
        cpasync16(bs_base0 + (unsigned)((bv*BSTR + bd*4)*4),
                  bptr + (size_t)bv*DD + bd*4);
    }
    asm volatile("cp.async.commit_group;");

    cudaGridDependencySynchronize();

    {
        float4 rA = arow ? __ldcs((const float4*)aptr)
                         : make_float4(0.f, 0.f, 0.f, 0.f);
        As[0][am*ASTR + avq*4 + 0] = rA.x;
        As[0][am*ASTR + avq*4 + 1] = rA.y;
        As[0][am*ASTR + avq*4 + 2] = rA.z;
        As[0][am*ASTR + avq*4 + 3] = rA.w;
        asm volatile("cp.async.wait_group 0;");
    }
    __syncthreads();

    float acc[16];
    #pragma unroll
    for (int i = 0; i < 16; ++i) acc[i] = 0.f;

    for (int ch = 0; ch < GNCH; ++ch){
        float4 rA;
        if (ch + 1 < GNCH){
            int vc = (ch + 1)*GKC;
            unsigned bsb = ((ch + 1) & 1) ? bs_base1 : bs_base0;
            #pragma unroll
            for (int j = 0; j < 4; ++j){
                int idx = tid + j*256, bv = idx >> 5, bd = idx & 31;
                cpasync16(bsb + (unsigned)((bv*BSTR + bd*4)*4),
                          bptr + (size_t)(vc + bv)*DD + bd*4);
            }
            asm volatile("cp.async.commit_group;");
            rA = arow ? __ldcs((const float4*)(aptr + vc))
                      : make_float4(0.f, 0.f, 0.f, 0.f);
        }
        if (active){
            const float* AsB = As[ch & 1] + (mt*16)*ASTR;
            const float* BsB = Bs[ch & 1] + ng*32;
            #pragma unroll
            for (int k8 = 0; k8 < GKC/8; ++k8){
                int kk = k8*8;
                unsigned a0 = __float_as_uint(AsB[(g    )*ASTR + kk + c    ]);
                unsigned a1 = __float_as_uint(AsB[(g + 8)*ASTR + kk + c    ]);
                unsigned a2 = __float_as_uint(AsB[(g    )*ASTR + kk + c + 4]);
                unsigned a3 = __float_as_uint(AsB[(g + 8)*ASTR + kk + c + 4]);
                #pragma unroll
                for (int nt = 0; nt < 4; ++nt){
                    unsigned b0 = __float_as_uint(BsB[(kk + c    )*BSTR + nt*8 + g]);
                    unsigned b1 = __float_as_uint(BsB[(kk + c + 4)*BSTR + nt*8 + g]);
                    mma168(acc + nt*4, a0, a1, a2, a3, b0, b1);
                }
            }
        }
        if (ch + 1 < GNCH){
            int bb = (ch + 1) & 1;
            As[bb][am*ASTR + avq*4 + 0] = rA.x;
            As[bb][am*ASTR + avq*4 + 1] = rA.y;
            As[bb][am*ASTR + avq*4 + 2] = rA.z;
            As[bb][am*ASTR + avq*4 + 3] = rA.w;
            asm volatile("cp.async.wait_group 0;");
        }
        __syncthreads();
    }

    if (active){
        int mbase = m0 + mt*16;
        int nbase = ng*32;
        #pragma unroll
        for (int nt = 0; nt < 4; ++nt){
            int col = nbase + nt*8 + 2*c;
            atomicAdd(&out[(size_t)(mbase + g    )*DD + col    ], acc[nt*4 + 0]);
            atomicAdd(&out[(size_t)(mbase + g    )*DD + col + 1], acc[nt*4 + 1]);
            atomicAdd(&out[(size_t)(mbase + g + 8)*DD + col    ], acc[nt*4 + 2]);
            atomicAdd(&out[(size_t)(mbase + g + 8)*DD + col + 1], acc[nt*4 + 3]);
        }
    }
}

// ---------------- launch ----------------
extern "C" void kernel_launch(void* const* d_in, const int* in_sizes, int n_in,
                              void* d_out, int out_size){
    (void)in_sizes; (void)n_in; (void)out_size;
    const int*   concepts = (const int*)  d_in[0];
    const int*   clen     = (const int*)  d_in[1];
    const int*   segl     = (const int*)  d_in[2];
    const float* embedw   = (const float*)d_in[3];
    const float* kb       = (const float*)d_in[4];
    const float* edge     = (const float*)d_in[5];
    const float* aff      = (const float*)d_in[6];
    const float* lam      = (const float*)d_in[7];
    float* out = (float*)d_out;

    ctx_kernel <<<BB, 1024>>>(concepts, clen, segl, embedw);

    cudaLaunchAttribute pdl[1];
    pdl[0].id = cudaLaunchAttributeProgrammaticStreamSerialization;
    pdl[0].val.programmaticStreamSerializationAllowed = 1;

    {
        cudaLaunchConfig_t cfg = {};
        cfg.gridDim = dim3(VV/8); cfg.blockDim = dim3(256);
        cfg.attrs = pdl; cfg.numAttrs = 1;
        cudaLaunchKernelEx(&cfg, cos_kernel, kb, out);
    }
    {
        cudaLaunchConfig_t cfg = {};
        cfg.gridDim = dim3(BB*SS); cfg.blockDim = dim3(NT_ATTN);
        cfg.attrs = pdl; cfg.numAttrs = 1;
        cudaLaunchKernelEx(&cfg, attn_kernel, concepts, clen, segl, edge, aff, lam);
    }
    {
        cudaLaunchConfig_t cfg = {};
        cfg.gridDim = dim3(BB, GKSPLIT); cfg.blockDim = dim3(256);
        cfg.attrs = pdl; cfg.numAttrs = 1;
        cudaLaunchKernelEx(&cfg, gemm_kernel, kb, segl, out);
    }
}